// round 17
// baseline (speedup 1.0000x reference)
#include <cuda_runtime.h>
#include <cuda_bf16.h>
#include <cstdint>

// Problem constants
#define BB   64
#define NN   4000
#define CIN  64
#define COUT 64
#define DD   10
#define KK   3
#define NP   4096
#define BC   4096

// ---------------- scratch (static device globals; no allocation) ------------
__device__ float g_A [(size_t)NP * NP];            // logits scratch (rows < NN)
__device__ float g_Y1[(size_t)NP * BC];
__device__ float g_Y2[(size_t)NP * BC];
__device__ __nv_bfloat16 g_Ah[(size_t)NP * NP];
__device__ __nv_bfloat16 g_Al[(size_t)NP * NP];
__device__ __nv_bfloat16 g_Bh[(size_t)NP * NP];
__device__ __nv_bfloat16 g_Bl[(size_t)NP * NP];
__device__ __nv_bfloat16 g_Wh[(size_t)NN * (KK * CIN) * COUT];   // [n][o][ki]
__device__ __nv_bfloat16 g_Wl[(size_t)NN * (KK * CIN) * COUT];

// ---------------- helpers ---------------------------------------------------
__device__ __forceinline__ uint32_t smem_u32(const void* p) {
    uint32_t a;
    asm("{ .reg .u64 t; cvta.to.shared.u64 t, %1; cvt.u32.u64 %0, t; }" : "=r"(a) : "l"(p));
    return a;
}

#define CP_ASYNC16(dst, src) \
    asm volatile("cp.async.cg.shared.global [%0], [%1], 16;" :: "r"(dst), "l"(src) : "memory")
#define CP_COMMIT() asm volatile("cp.async.commit_group;" ::: "memory")

__device__ __forceinline__ void ldsm_x4(uint32_t* d, uint32_t addr) {
    asm volatile("ldmatrix.sync.aligned.m8n8.x4.shared.b16 {%0,%1,%2,%3}, [%4];"
                 : "=r"(d[0]), "=r"(d[1]), "=r"(d[2]), "=r"(d[3]) : "r"(addr));
}

__device__ __forceinline__ void mma_bf16(float* c, const uint32_t* a, const uint32_t* b) {
    asm volatile("mma.sync.aligned.m16n8k16.row.col.f32.bf16.bf16.f32 "
                 "{%0,%1,%2,%3}, {%4,%5,%6,%7}, {%8,%9}, {%0,%1,%2,%3};"
                 : "+f"(c[0]), "+f"(c[1]), "+f"(c[2]), "+f"(c[3])
                 : "r"(a[0]), "r"(a[1]), "r"(a[2]), "r"(a[3]), "r"(b[0]), "r"(b[1]));
}

__device__ __forceinline__ void split2(float a, __nv_bfloat16& h, __nv_bfloat16& l) {
    h = __float2bfloat16(a);
    l = __float2bfloat16(a - __bfloat162float(h));
}

// ---------------- kernel 1: adjacency + softmax + bf16 split (fused) --------
__global__ __launch_bounds__(256) void build_adj(const float* __restrict__ emb) {
    const int n   = blockIdx.x;
    const int tid = threadIdx.x;
    float* row = &g_A[(size_t)n * NP];
    __shared__ float red[256];

    __nv_bfloat162* AH = reinterpret_cast<__nv_bfloat162*>(g_Ah + (size_t)n * NP);
    __nv_bfloat162* AL = reinterpret_cast<__nv_bfloat162*>(g_Al + (size_t)n * NP);

    if (n >= NN) {
        const __nv_bfloat162 z = __halves2bfloat162(__float2bfloat16(0.f), __float2bfloat16(0.f));
        for (int m2 = tid; m2 < NP / 2; m2 += 256) { AH[m2] = z; AL[m2] = z; }
        return;
    }
    float e[DD];
#pragma unroll
    for (int d = 0; d < DD; ++d) e[d] = emb[n * DD + d];

    float lmax = 0.0f;
    for (int m = tid; m < NN; m += 256) {
        const float* em = &emb[m * DD];
        float s = 0.0f;
#pragma unroll
        for (int d = 0; d < DD; ++d) s = fmaf(e[d], em[d], s);
        s = fmaxf(s, 0.0f);
        row[m] = s;
        lmax = fmaxf(lmax, s);
    }
    red[tid] = lmax; __syncthreads();
    for (int s = 128; s > 0; s >>= 1) {
        if (tid < s) red[tid] = fmaxf(red[tid], red[tid + s]);
        __syncthreads();
    }
    const float rmax = red[0];
    __syncthreads();

    float lsum = 0.0f;
    for (int m = tid; m < NN; m += 256) {
        float v = __expf(row[m] - rmax);
        row[m] = v;
        lsum += v;
    }
    red[tid] = lsum; __syncthreads();
    for (int s = 128; s > 0; s >>= 1) {
        if (tid < s) red[tid] += red[tid + s];
        __syncthreads();
    }
    const float inv = 1.0f / red[0];

    for (int m2 = tid; m2 < NP / 2; m2 += 256) {
        const int m = 2 * m2;
        const float v0 = (m < NN)     ? row[m]     * inv : 0.0f;
        const float v1 = (m + 1 < NN) ? row[m + 1] * inv : 0.0f;
        __nv_bfloat16 h0, l0, h1, l1;
        split2(v0, h0, l0); split2(v1, h1, l1);
        AH[m2] = __halves2bfloat162(h0, h1);
        AL[m2] = __halves2bfloat162(l0, l1);
    }
}

// ---------------- kernel 2: pack+transpose+split x -> B[(b,c)][m] -----------
__global__ __launch_bounds__(256) void pack_split_x(const float* __restrict__ x) {
    __shared__ float s[64][132];
    const int b  = blockIdx.y;
    const int m0 = blockIdx.x * 128;
    const int tid = threadIdx.x;
    const float4* x4 = reinterpret_cast<const float4*>(x);

#pragma unroll
    for (int it = 0; it < 8; ++it) {
        const int i  = it * 16 + (tid >> 4);
        const int c0 = (tid & 15) * 4;
        const int m  = m0 + i;
        float4 v = make_float4(0.f, 0.f, 0.f, 0.f);
        if (m < NN) v = x4[((size_t)b * NN + m) * 16 + (tid & 15)];
        s[c0 + 0][i] = v.x; s[c0 + 1][i] = v.y; s[c0 + 2][i] = v.z; s[c0 + 3][i] = v.w;
    }
    __syncthreads();

    __nv_bfloat162* BH = reinterpret_cast<__nv_bfloat162*>(g_Bh);
    __nv_bfloat162* BL = reinterpret_cast<__nv_bfloat162*>(g_Bl);
#pragma unroll
    for (int it = 0; it < 16; ++it) {
        const int c = it * 4 + (tid >> 6);
        const int j = tid & 63;
        __nv_bfloat16 h0, l0, h1, l1;
        split2(s[c][2 * j],     h0, l0);
        split2(s[c][2 * j + 1], h1, l1);
        const size_t off = (size_t)(b * 64 + c) * (NP / 2) + (m0 >> 1) + j;
        BH[off] = __halves2bfloat162(h0, h1);
        BL[off] = __halves2bfloat162(l0, l1);
    }
}

// ---------------- kernel 3: transpose+split Y1[k][n] -> B[n][k] -------------
__global__ __launch_bounds__(256) void split_y1_k() {
    __shared__ float t[32][33];
    const int k0 = blockIdx.x * 32;
    const int n0 = blockIdx.y * 32;
    const int tx = threadIdx.x;
    const int ty = threadIdx.y;
#pragma unroll
    for (int q = 0; q < 4; ++q)
        t[ty + 8 * q][tx] = g_Y1[(size_t)(k0 + ty + 8 * q) * BC + n0 + tx];
    __syncthreads();
#pragma unroll
    for (int q = 0; q < 4; ++q) {
        const float a = t[tx][ty + 8 * q];
        __nv_bfloat16 h, l; split2(a, h, l);
        const size_t off = (size_t)(n0 + ty + 8 * q) * NP + k0 + tx;
        g_Bh[off] = h;
        g_Bl[off] = l;
    }
}

// ---------------- kernel 4: per-node weight pool W = emb @ wp ---------------
// W transposed to [n][o][ki], split hi/lo bf16. Thread caches its wp slice in
// registers once and reuses it for all 32 nodes of the block.
__global__ __launch_bounds__(256) void gen_w(const float* __restrict__ emb,
                                             const float* __restrict__ wp) {
    extern __shared__ float gsm[];
    float* swp  = gsm;                 // [10][64 o][24 kk]
    float* semb = gsm + 15360;         // [32][10]

    const int kc0 = blockIdx.x * 24;
    const int nt0 = blockIdx.y * 32;
    const int tid = threadIdx.x;

#pragma unroll
    for (int i = 0; i < 60; ++i) {
        const int f = tid + i * 256;
        const int d = f / 1536;
        const int r = f - d * 1536;
        const int o  = r & 63;
        const int kk = r >> 6;
        swp[d * 1536 + o * 24 + kk] = wp[((size_t)d * 192 + kc0 + kk) * 64 + o];
    }
    if (tid < 256) semb[tid] = emb[(size_t)nt0 * DD + tid];
    if (tid < 64)  semb[256 + tid] = emb[(size_t)nt0 * DD + 256 + tid];
    __syncthreads();

    // per-thread items: (o, kk-pair); cache wp slice in registers
    int oo[3], kp[3];
    float w[3][DD][2];
#pragma unroll
    for (int it = 0; it < 3; ++it) {
        const int f = tid + it * 256;          // 0..767
        oo[it] = f / 12;
        kp[it] = f - oo[it] * 12;
#pragma unroll
        for (int d = 0; d < DD; ++d) {
            const float2 v = *reinterpret_cast<const float2*>(
                &swp[d * 1536 + oo[it] * 24 + 2 * kp[it]]);
            w[it][d][0] = v.x; w[it][d][1] = v.y;
        }
    }

    for (int nn = 0; nn < 32; ++nn) {
        const int n = nt0 + nn;
        float e[DD];
#pragma unroll
        for (int d = 0; d < DD; ++d) e[d] = semb[nn * DD + d];
#pragma unroll
        for (int it = 0; it < 3; ++it) {
            float s0 = 0.0f, s1 = 0.0f;
#pragma unroll
            for (int d = 0; d < DD; ++d) {
                s0 = fmaf(e[d], w[it][d][0], s0);
                s1 = fmaf(e[d], w[it][d][1], s1);
            }
            __nv_bfloat16 h0, l0, h1, l1;
            split2(s0, h0, l0); split2(s1, h1, l1);
            const size_t off = ((size_t)n * 12288 + (size_t)oo[it] * 192 + kc0 + 2 * kp[it]) >> 1;
            reinterpret_cast<__nv_bfloat162*>(g_Wh)[off] = __halves2bfloat162(h0, h1);
            reinterpret_cast<__nv_bfloat162*>(g_Wl)[off] = __halves2bfloat162(l0, l1);
        }
    }
}

// ---------------- kernel 5: mma.sync bf16x3 GEMM, 256x128 CTA tile ----------
// C[m][n] = alpha * sum_k (Ah+Al)[m][k]*(Bh+Bl)[n][k] + beta * Cin
// 8 warps as 4m x 2n (warp tile 64x64), 4-stage cp.async.
#define A_TILE_B   (256 * 64)                 // per-op A tile bytes (16KB)
#define B_TILE_B   (128 * 64)                 // per-op B tile bytes (8KB)
#define STAGE_BYTES (2 * A_TILE_B + 2 * B_TILE_B)   // 48KB
#define GSTAGES     4
#define GEMM_SMEM   (GSTAGES * STAGE_BYTES)   // 192KB
#define OFF_AL  A_TILE_B
#define OFF_BH  (2 * A_TILE_B)
#define OFF_BL  (2 * A_TILE_B + B_TILE_B)

__device__ __forceinline__ uint32_t sw_addr(uint32_t tileBase, int r, int c) {
    return tileBase + r * 64 + (((c ^ ((r >> 1) & 3))) << 4);
}

__global__ __launch_bounds__(256, 1) void gemm_mma(
    const __nv_bfloat16* __restrict__ Ah, const __nv_bfloat16* __restrict__ Al,
    const __nv_bfloat16* __restrict__ Bh, const __nv_bfloat16* __restrict__ Bl,
    const float* __restrict__ cin_x, float* __restrict__ C,
    float alpha, float beta, int cin_mode)
{
    extern __shared__ char smem[];
    const uint32_t sb = smem_u32(smem);
    const int tid  = threadIdx.x;
    const int wid  = tid >> 5;
    const int lane = tid & 31;
    const int bm = blockIdx.y * 256;
    const int bn = blockIdx.x * 128;
    const int wm = (wid >> 1) * 64;     // 4 warps in m
    const int wn = (wid & 1) * 64;      // 2 warps in n

    auto load_chunk = [&](int ck, int s) {
        const uint32_t stage = sb + s * STAGE_BYTES;
        const size_t kb = (size_t)ck * 64;
        // A: 2048 x 16B over 8 iters
#pragma unroll
        for (int i = 0; i < 8; ++i) {
            const int idx = tid + i * 256;
            const int aop = idx >> 10;              // 0=Ah 1=Al
            const int r   = (idx >> 2) & 255;
            const int c   = idx & 3;
            const char* gb = (const char*)(aop == 0 ? Ah : Al)
                           + (size_t)(bm + r) * (NP * 2) + kb;
            CP_ASYNC16(sw_addr(stage + aop * A_TILE_B, r, c), gb + c * 16);
        }
        // B: 1024 x 16B over 4 iters
#pragma unroll
        for (int i = 0; i < 4; ++i) {
            const int j   = tid + i * 256;
            const int bop = j >> 9;                 // 0=Bh 1=Bl
            const int r   = (j >> 2) & 127;
            const int c   = j & 3;
            const char* gb = (const char*)(bop == 0 ? Bh : Bl)
                           + (size_t)(bn + r) * (NP * 2) + kb;
            CP_ASYNC16(sw_addr(stage + OFF_BH + bop * B_TILE_B, r, c), gb + c * 16);
        }
        CP_COMMIT();
    };

    float acc[4][8][4];
#pragma unroll
    for (int mt = 0; mt < 4; ++mt)
#pragma unroll
        for (int nt = 0; nt < 8; ++nt)
#pragma unroll
            for (int q = 0; q < 4; ++q) acc[mt][nt][q] = 0.0f;

    load_chunk(0, 0);
    load_chunk(1, 1);
    load_chunk(2, 2);

    for (int ck = 0; ck < 128; ++ck) {
        const int s = ck & 3;
        if (ck < 126)       asm volatile("cp.async.wait_group 2;" ::: "memory");
        else if (ck == 126) asm volatile("cp.async.wait_group 1;" ::: "memory");
        else                asm volatile("cp.async.wait_group 0;" ::: "memory");
        __syncthreads();

        if (ck + 3 < 128) load_chunk(ck + 3, (ck + 3) & 3);   // overlaps MMAs

        const uint32_t stage = sb + s * STAGE_BYTES;
#pragma unroll
        for (int ks = 0; ks < 2; ++ks) {
            uint32_t ahf[4][4], alf[4][4];
            const int arow = wm + (lane & 15);
            const int ac   = ks * 2 + (lane >> 4);
#pragma unroll
            for (int mt = 0; mt < 4; ++mt) {
                ldsm_x4(ahf[mt], sw_addr(stage, arow + mt * 16, ac));
                ldsm_x4(alf[mt], sw_addr(stage + OFF_AL, arow + mt * 16, ac));
            }
            const int brow = (lane & 7) + ((lane >> 4) << 3);
            const int bc   = ks * 2 + ((lane >> 3) & 1);
#pragma unroll
            for (int p = 0; p < 4; ++p) {
                uint32_t th[4], tl[4];
                ldsm_x4(th, sw_addr(stage + OFF_BH, wn + p * 16 + brow, bc));
                ldsm_x4(tl, sw_addr(stage + OFF_BL, wn + p * 16 + brow, bc));
#pragma unroll
                for (int mt = 0; mt < 4; ++mt) {
                    mma_bf16(acc[mt][2 * p],     ahf[mt], th);
                    mma_bf16(acc[mt][2 * p + 1], ahf[mt], th + 2);
                    mma_bf16(acc[mt][2 * p],     ahf[mt], tl);
                    mma_bf16(acc[mt][2 * p + 1], ahf[mt], tl + 2);
                    mma_bf16(acc[mt][2 * p],     alf[mt], th);
                    mma_bf16(acc[mt][2 * p + 1], alf[mt], th + 2);
                }
            }
        }
    }

    const int r0 = lane >> 2;
    const int c0 = (lane & 3) * 2;
#pragma unroll
    for (int mt = 0; mt < 4; ++mt) {
#pragma unroll
        for (int nt = 0; nt < 8; ++nt) {
            const int n = bn + wn + nt * 8 + c0;
#pragma unroll
            for (int h = 0; h < 2; ++h) {
                const int m = bm + wm + mt * 16 + r0 + h * 8;
                float v0 = alpha * acc[mt][nt][h * 2 + 0];
                float v1 = alpha * acc[mt][nt][h * 2 + 1];
                if (cin_mode == 1 && m < NN) {
                    const float* cb = cin_x + ((size_t)(n >> 6) * NN + m) * 64 + (n & 63);
                    v0 = fmaf(beta, cb[0], v0);
                    v1 = fmaf(beta, cb[1], v1);
                }
                float2 o = make_float2(v0, v1);
                *reinterpret_cast<float2*>(C + (size_t)m * BC + n) = o;
            }
        }
    }
}

// ---------------- kernel 6: per-node epilogue on tensor cores ---------------
#define EP_STRIDE 200
#define EP_SMEM   (4 * 64 * EP_STRIDE * 2 + 256)

__global__ __launch_bounds__(256, 2) void node_mma(const float* __restrict__ x,
                                                   const float* __restrict__ emb,
                                                   const float* __restrict__ bp,
                                                   float* __restrict__ out) {
    extern __shared__ char esm[];
    __nv_bfloat16* sA = reinterpret_cast<__nv_bfloat16*>(esm);
    float* sBias = reinterpret_cast<float*>(esm + 4 * 64 * EP_STRIDE * 2);
    const uint32_t sb    = smem_u32(esm);
    const uint32_t wbase = sb + 2u * 64 * EP_STRIDE * 2;

    const int n    = blockIdx.x;
    const int tid  = threadIdx.x;
    const int lane = tid & 31;
    const int wid  = tid >> 5;

    {
        const char* gH = (const char*)(g_Wh + (size_t)n * 12288);
        const char* gL = (const char*)(g_Wl + (size_t)n * 12288);
#pragma unroll
        for (int i = 0; i < 6; ++i) {
            const int f = tid + i * 256;
            const int o = f / 24, c = f - o * 24;
            CP_ASYNC16(wbase + o * 400 + c * 16, gH + o * 384 + c * 16);
            CP_ASYNC16(wbase + 64 * 400 + o * 400 + c * 16, gL + o * 384 + c * 16);
        }
        CP_COMMIT();
    }
    if (tid < 64) {
        float s = 0.0f;
#pragma unroll
        for (int d = 0; d < DD; ++d) s = fmaf(emb[n * DD + d], bp[d * 64 + tid], s);
        sBias[tid] = s;
    }
    {
        __nv_bfloat16* sAh = sA;
        __nv_bfloat16* sAl = sA + 64 * EP_STRIDE;
        auto put4 = [&](int b, int col, float4 v) {
            __nv_bfloat16 h0,l0,h1,l1,h2,l2,h3,l3;
            split2(v.x,h0,l0); split2(v.y,h1,l1); split2(v.z,h2,l2); split2(v.w,h3,l3);
            __nv_bfloat162* ph = reinterpret_cast<__nv_bfloat162*>(sAh + b * EP_STRIDE + col);
            __nv_bfloat162* pl = reinterpret_cast<__nv_bfloat162*>(sAl + b * EP_STRIDE + col);
            ph[0] = __halves2bfloat162(h0, h1); ph[1] = __halves2bfloat162(h2, h3);
            pl[0] = __halves2bfloat162(l0, l1); pl[1] = __halves2bfloat162(l2, l3);
        };
        const float4* x4  = reinterpret_cast<const float4*>(x);
        const float4* y1r = reinterpret_cast<const float4*>(g_Y1 + (size_t)n * BC);
        const float4* y2r = reinterpret_cast<const float4*>(g_Y2 + (size_t)n * BC);
#pragma unroll
        for (int i = 0; i < 4; ++i) {
            const int f = tid + i * 256;
            const int b = f >> 4, i4 = f & 15;
            put4(b, i4 * 4,       x4[((size_t)b * NN + n) * 16 + i4]);
            put4(b, 64 + i4 * 4,  y1r[f]);
            put4(b, 128 + i4 * 4, y2r[f]);
        }
    }
    asm volatile("cp.async.wait_group 0;" ::: "memory");
    __syncthreads();

    const int mt = wid >> 1;
    const int n0 = (wid & 1) * 32;
    float acc[4][4];
#pragma unroll
    for (int nt = 0; nt < 4; ++nt)
#pragma unroll
        for (int q = 0; q < 4; ++q) acc[nt][q] = 0.0f;

    const uint32_t aH = sb;
    const uint32_t aL = sb + 64u * EP_STRIDE * 2;
    const uint32_t wH = wbase;
    const uint32_t wL = wbase + 64u * 400;
#pragma unroll
    for (int ks = 0; ks < 12; ++ks) {
        uint32_t ahf[4], alf[4], bhf[4][2], blf[4][2];
        const int arow = mt * 16 + (lane & 15);
        const uint32_t acol = ks * 32 + (lane >> 4) * 16;
        ldsm_x4(ahf, aH + arow * 400 + acol);
        ldsm_x4(alf, aL + arow * 400 + acol);
        const int brow = (lane & 7) + ((lane >> 4) << 3);
        const uint32_t bcol = ks * 32 + ((lane >> 3) & 1) * 16;
#pragma unroll
        for (int p = 0; p < 2; ++p) {
            uint32_t t[4];
            ldsm_x4(t, wH + (n0 + p * 16 + brow) * 400 + bcol);
            bhf[2*p][0] = t[0]; bhf[2*p][1] = t[1];
            bhf[2*p+1][0] = t[2]; bhf[2*p+1][1] = t[3];
            ldsm_x4(t, wL + (n0 + p * 16 + brow) * 400 + bcol);
            blf[2*p][0] = t[0]; blf[2*p][1] = t[1];
            blf[2*p+1][0] = t[2]; blf[2*p+1][1] = t[3];
        }
#pragma unroll
        for (int nt = 0; nt < 4; ++nt) {
            mma_bf16(acc[nt], ahf, bhf[nt]);
            mma_bf16(acc[nt], ahf, blf[nt]);
            mma_bf16(acc[nt], alf, bhf[nt]);
        }
    }

    const int r0 = lane >> 2;
    const int c0 = (lane & 3) * 2;
#pragma unroll
    for (int nt = 0; nt < 4; ++nt) {
        const int o = n0 + nt * 8 + c0;
        const float b0 = sBias[o], b1 = sBias[o + 1];
#pragma unroll
        for (int h = 0; h < 2; ++h) {
            const int b = mt * 16 + r0 + h * 8;
            float2 v = make_float2(acc[nt][h * 2 + 0] + b0, acc[nt][h * 2 + 1] + b1);
            *reinterpret_cast<float2*>(out + ((size_t)b * NN + n) * 64 + o) = v;
        }
    }
}

// ---------------- launch ----------------------------------------------------
extern "C" void kernel_launch(void* const* d_in, const int* in_sizes, int n_in,
                              void* d_out, int out_size) {
    const float* x   = (const float*)d_in[0];   // [64,4000,64]
    const float* emb = (const float*)d_in[1];   // [4000,10]
    const float* wp  = (const float*)d_in[2];   // [10,3,64,64]
    const float* bp  = (const float*)d_in[3];   // [10,64]
    float* out = (float*)d_out;

    float *Y1, *Y2;
    __nv_bfloat16 *Ah, *Al, *Bh, *Bl;
    cudaGetSymbolAddress((void**)&Y1, g_Y1);
    cudaGetSymbolAddress((void**)&Y2, g_Y2);
    cudaGetSymbolAddress((void**)&Ah, g_Ah);
    cudaGetSymbolAddress((void**)&Al, g_Al);
    cudaGetSymbolAddress((void**)&Bh, g_Bh);
    cudaGetSymbolAddress((void**)&Bl, g_Bl);

    // 1. adjacency + softmax + bf16 split (fused)
    build_adj<<<NP, 256>>>(emb);

    // 2. pack + transpose + split X -> B[(b,c)][m]
    pack_split_x<<<dim3(NP / 128, BB), 256>>>(x);

    // 3. per-node weight pools
    const int gw_smem = (15360 + 320) * sizeof(float);
    cudaFuncSetAttribute(gen_w, cudaFuncAttributeMaxDynamicSharedMemorySize, gw_smem);
    gen_w<<<dim3(8, 125), 256, gw_smem>>>(emb, wp);

    // 4. Y1 = A @ X
    cudaFuncSetAttribute(gemm_mma, cudaFuncAttributeMaxDynamicSharedMemorySize, GEMM_SMEM);
    dim3 gg(NP / 128, NP / 256);
    gemm_mma<<<gg, 256, GEMM_SMEM>>>(Ah, Al, Bh, Bl, nullptr, Y1, 1.0f, 0.0f, 0);

    // 5. transpose + split Y1 -> B[n][k]
    split_y1_k<<<dim3(NP / 32, NP / 32), dim3(32, 8)>>>();

    // 6. Y2 = 2 A @ Y1 - X
    gemm_mma<<<gg, 256, GEMM_SMEM>>>(Ah, Al, Bh, Bl, x, Y2, 2.0f, -1.0f, 1);

    // 7. per-node contraction on tensor cores
    cudaFuncSetAttribute(node_mma, cudaFuncAttributeMaxDynamicSharedMemorySize, EP_SMEM);
    node_mma<<<NN, 256, EP_SMEM>>>(x, emb, bp, out);
}